// round 3
// baseline (speedup 1.0000x reference)
#include <cuda_runtime.h>
#include <math.h>

#define Bq 4
#define Lq 4096
#define Hq 8
#define Dq 64
#define SK 9
#define U  9
#define BH (Bq*Hq)

// scratch (static __device__ arrays — no allocation)
__device__ float g_M[BH * Lq];
__device__ int   g_top[BH * U];
__device__ float g_vmean[BH * Dq];

// ---------------------------------------------------------------------------
// Kernel 1: M[b,h,l] = max_s(Q[l]·K[idx[l,s]]) - sum_s(...)/L
// one warp per (b,h,l)
// ---------------------------------------------------------------------------
__global__ void __launch_bounds__(256)
k_sample_scores(const float* __restrict__ q,
                const float* __restrict__ k,
                const int*   __restrict__ idx)
{
    int warp = (blockIdx.x * blockDim.x + threadIdx.x) >> 5;
    int lane = threadIdx.x & 31;
    if (warp >= BH * Lq) return;
    int l  = warp % Lq;
    int bh = warp / Lq;
    int b = bh / Hq, h = bh % Hq;

    const float* qrow = q + ((size_t)(b * Lq + l) * Hq + h) * Dq;
    float q0 = qrow[lane];
    float q1 = qrow[lane + 32];

    float mx = -INFINITY, sm = 0.f;
#pragma unroll
    for (int s = 0; s < SK; s++) {
        int ks = idx[l * SK + s];
        const float* krow = k + ((size_t)(b * Lq + ks) * Hq + h) * Dq;
        float p = q0 * krow[lane] + q1 * krow[lane + 32];
#pragma unroll
        for (int o = 16; o > 0; o >>= 1) p += __shfl_xor_sync(0xffffffffu, p, o);
        mx = fmaxf(mx, p);
        sm += p;
    }
    if (lane == 0) g_M[bh * Lq + l] = mx - sm * (1.0f / (float)Lq);
}

// ---------------------------------------------------------------------------
// Kernel 2: top-9 (descending, ties -> lower index) per (b,h)
// one block (128 threads) per bh
// ---------------------------------------------------------------------------
__global__ void __launch_bounds__(128)
k_topk()
{
    int bh = blockIdx.x;
    __shared__ float sm[Lq];
    __shared__ float rv[128];
    __shared__ int   ri[128];
    int t = threadIdx.x;

    for (int i = t; i < Lq; i += 128) sm[i] = g_M[bh * Lq + i];
    __syncthreads();

    for (int r = 0; r < U; r++) {
        float bv = -INFINITY; int bi = 0x7fffffff;
        for (int i = t; i < Lq; i += 128) {
            float v = sm[i];
            if (v > bv || (v == bv && i < bi)) { bv = v; bi = i; }
        }
        rv[t] = bv; ri[t] = bi;
        __syncthreads();
        for (int o = 64; o > 0; o >>= 1) {
            if (t < o) {
                float v2 = rv[t + o]; int i2 = ri[t + o];
                if (v2 > rv[t] || (v2 == rv[t] && i2 < ri[t])) { rv[t] = v2; ri[t] = i2; }
            }
            __syncthreads();
        }
        if (t == 0) { g_top[bh * U + r] = ri[0]; sm[ri[0]] = -INFINITY; }
        __syncthreads();
    }
}

// ---------------------------------------------------------------------------
// Kernel 3: V mean over L per (b,h,d). one block (512 threads) per bh
// ---------------------------------------------------------------------------
__global__ void __launch_bounds__(512, 1)
k_vmean(const float* __restrict__ v)
{
    int bh = blockIdx.x;
    int b = bh / Hq, h = bh % Hq;
    int t = threadIdx.x;
    int d = t & 63, g = t >> 6;        // 8 l-groups x 64 d
    float acc = 0.f;
    for (int l = g; l < Lq; l += 8)
        acc += v[((size_t)(b * Lq + l) * Hq + h) * Dq + d];
    __shared__ float red[512];
    red[t] = acc;
    __syncthreads();
    for (int o = 256; o >= 64; o >>= 1) {
        if (t < o) red[t] += red[t + o];
        __syncthreads();
    }
    if (t < 64) g_vmean[bh * Dq + t] = red[t] * (1.0f / (float)Lq);
}

// ---------------------------------------------------------------------------
// Kernel 4: broadcast V-mean into context output (B,L,H,D layout)
// ---------------------------------------------------------------------------
__global__ void __launch_bounds__(256)
k_bcast(float* __restrict__ out)
{
    size_t i = (size_t)blockIdx.x * blockDim.x + threadIdx.x;
    const size_t total = (size_t)Bq * Lq * Hq * Dq;
    if (i >= total) return;
    int d = (int)(i & 63);
    int h = (int)((i >> 6) & (Hq - 1));
    int b = (int)(i / ((size_t)Lq * Hq * Dq));
    out[i] = g_vmean[(b * Hq + h) * Dq + d];
}

// ---------------------------------------------------------------------------
// Kernel 5: scores -> softmax -> attn write -> ctx -> scatter into context.
// one block (512 threads) per (b,h); K and V each read once per block.
// Dynamic smem: qr[U*D] | at[U*L] | red[512] | cred[8*U*D]
// ---------------------------------------------------------------------------
#define SMEM_FLOATS (U*Dq + U*Lq + 512 + 8*U*Dq)

__global__ void __launch_bounds__(512, 1)
k_attn(const float* __restrict__ q,
       const float* __restrict__ k,
       const float* __restrict__ v,
       float* __restrict__ out)
{
    extern __shared__ float smem[];
    int bh = blockIdx.x;
    int b = bh / Hq, h = bh % Hq;
    int t = threadIdx.x;

    float* qr   = smem;                 // U*D = 576
    float* at   = qr + U * Dq;          // U*L
    float* red  = at + U * Lq;          // 512
    float* cred = red + 512;            // 8*U*D

    // load Q_reduce rows (top-u queries) — strided: U*Dq (576) > blockDim (512)
    for (int i = t; i < U * Dq; i += 512) {
        int r = i / Dq, d = i % Dq;
        int l = g_top[bh * U + r];
        qr[i] = q[((size_t)(b * Lq + l) * Hq + h) * Dq + d];
    }
    __syncthreads();

    const float scale = 0.125f;         // 1/sqrt(64)

    // scores: each thread handles L/512 = 8 keys, computes 9 dots each
    for (int kk = t; kk < Lq; kk += 512) {
        const float4* krow = (const float4*)(k + ((size_t)(b * Lq + kk) * Hq + h) * Dq);
        float dot[U];
#pragma unroll
        for (int r = 0; r < U; r++) dot[r] = 0.f;
#pragma unroll
        for (int i = 0; i < Dq / 4; i++) {
            float4 kv = krow[i];
#pragma unroll
            for (int r = 0; r < U; r++) {
                dot[r] += kv.x * qr[r * Dq + 4 * i + 0]
                        + kv.y * qr[r * Dq + 4 * i + 1]
                        + kv.z * qr[r * Dq + 4 * i + 2]
                        + kv.w * qr[r * Dq + 4 * i + 3];
            }
        }
#pragma unroll
        for (int r = 0; r < U; r++) at[r * Lq + kk] = dot[r] * scale;
    }
    __syncthreads();

    float* attn_out = out + (size_t)Bq * Lq * Hq * Dq + (size_t)bh * U * Lq;

    // per-row softmax + attn output write
    for (int r = 0; r < U; r++) {
        float* row = at + r * Lq;
        float mx = -INFINITY;
        for (int kk = t; kk < Lq; kk += 512) mx = fmaxf(mx, row[kk]);
        red[t] = mx; __syncthreads();
        for (int o = 256; o > 0; o >>= 1) {
            if (t < o) red[t] = fmaxf(red[t], red[t + o]);
            __syncthreads();
        }
        mx = red[0]; __syncthreads();

        float sm = 0.f;
        for (int kk = t; kk < Lq; kk += 512) {
            float e = expf(row[kk] - mx);
            row[kk] = e;
            sm += e;
        }
        red[t] = sm; __syncthreads();
        for (int o = 256; o > 0; o >>= 1) {
            if (t < o) red[t] += red[t + o];
            __syncthreads();
        }
        float inv = 1.0f / red[0]; __syncthreads();

        for (int kk = t; kk < Lq; kk += 512) {
            float a = row[kk] * inv;
            row[kk] = a;
            attn_out[r * Lq + kk] = a;
        }
        __syncthreads();
    }

    // ctx_top[r][d] = sum_k attn[r][k] * V[k][d]; 8 k-groups x 64 d
    {
        int d = t & 63, g = t >> 6;
        float acc[U];
#pragma unroll
        for (int r = 0; r < U; r++) acc[r] = 0.f;
        for (int kk = g; kk < Lq; kk += 8) {
            float vv = v[((size_t)(b * Lq + kk) * Hq + h) * Dq + d];
#pragma unroll
            for (int r = 0; r < U; r++) acc[r] += at[r * Lq + kk] * vv;
        }
#pragma unroll
        for (int r = 0; r < U; r++) cred[(g * U + r) * Dq + d] = acc[r];
    }
    __syncthreads();

    // reduce k-groups and scatter into context at top indices
    for (int i = t; i < U * Dq; i += 512) {
        int r = i / Dq, dd = i % Dq;
        float s = 0.f;
#pragma unroll
        for (int gg = 0; gg < 8; gg++) s += cred[(gg * U + r) * Dq + dd];
        int l = g_top[bh * U + r];
        out[((size_t)(b * Lq + l) * Hq + h) * Dq + dd] = s;
    }
}

// ---------------------------------------------------------------------------
extern "C" void kernel_launch(void* const* d_in, const int* in_sizes, int n_in,
                              void* d_out, int out_size)
{
    const float* q   = (const float*)d_in[0];
    const float* k   = (const float*)d_in[1];
    const float* v   = (const float*)d_in[2];
    const int*   idx = (const int*)d_in[3];
    float* out = (float*)d_out;

    (void)in_sizes; (void)n_in; (void)out_size;

    // kernel 1: one warp per (b,h,l) -> 131072 warps, 8 warps/block
    {
        int warps = BH * Lq;
        int blocks = warps / 8;
        k_sample_scores<<<blocks, 256>>>(q, k, idx);
    }

    // kernel 2: top-9 per (b,h)
    k_topk<<<BH, 128>>>();

    // kernel 3: V mean
    k_vmean<<<BH, 512>>>(v);

    // kernel 4: broadcast mean into context
    {
        size_t total = (size_t)Bq * Lq * Hq * Dq;
        int blocks = (int)((total + 255) / 256);
        k_bcast<<<blocks, 256>>>(out);
    }

    // kernel 5: fused scores/softmax/ctx/scatter
    {
        static int smem_set = 0;
        size_t smem_bytes = (size_t)SMEM_FLOATS * sizeof(float);
        if (!smem_set) {
            cudaFuncSetAttribute(k_attn, cudaFuncAttributeMaxDynamicSharedMemorySize,
                                 (int)smem_bytes);
            smem_set = 1;
        }
        k_attn<<<BH, 512, smem_bytes>>>(q, k, v, out);
    }
}

// round 4
// speedup vs baseline: 1.5853x; 1.5853x over previous
#include <cuda_runtime.h>
#include <math.h>

#define Bq 4
#define Lq 4096
#define Hq 8
#define Dq 64
#define SK 9
#define U  9
#define BH (Bq*Hq)
#define NCH 8
#define CHK (Lq/NCH)   // 512

// scratch (static __device__ arrays — no allocation)
__device__ float  g_M[BH * Lq];
__device__ int    g_top[BH * U];
__device__ float4 g_vmean4[BH * (Dq/4)];
__device__ float  g_vpart[BH * NCH * Dq];
__device__ float  g_scores[BH * U * Lq];        // raw scores, then normalized attn
__device__ float  g_ctxpart[BH * NCH * U * Dq];

// ---------------------------------------------------------------------------
// Kernel 1: M[b,h,l] = max_s(Q[l]·K[idx[l,s]]) - sum_s(...)/L ; one warp per (b,h,l)
// ---------------------------------------------------------------------------
__global__ void __launch_bounds__(256)
k_sample_scores(const float* __restrict__ q,
                const float* __restrict__ k,
                const int*   __restrict__ idx)
{
    int warp = (blockIdx.x * blockDim.x + threadIdx.x) >> 5;
    int lane = threadIdx.x & 31;
    if (warp >= BH * Lq) return;
    int l  = warp % Lq;
    int bh = warp / Lq;
    int b = bh / Hq, h = bh % Hq;

    const float* qrow = q + ((size_t)(b * Lq + l) * Hq + h) * Dq;
    float q0 = qrow[lane];
    float q1 = qrow[lane + 32];

    float mx = -INFINITY, sm = 0.f;
#pragma unroll
    for (int s = 0; s < SK; s++) {
        int ks = idx[l * SK + s];
        const float* krow = k + ((size_t)(b * Lq + ks) * Hq + h) * Dq;
        float p = q0 * krow[lane] + q1 * krow[lane + 32];
#pragma unroll
        for (int o = 16; o > 0; o >>= 1) p += __shfl_xor_sync(0xffffffffu, p, o);
        mx = fmaxf(mx, p);
        sm += p;
    }
    if (lane == 0) g_M[bh * Lq + l] = mx - sm * (1.0f / (float)Lq);
}

// ---------------------------------------------------------------------------
// Kernel 2: top-9 (descending, ties -> lower index) per (b,h); one block per bh
// ---------------------------------------------------------------------------
__global__ void __launch_bounds__(128)
k_topk()
{
    int bh = blockIdx.x;
    __shared__ float sm[Lq];
    __shared__ float rv[128];
    __shared__ int   ri[128];
    int t = threadIdx.x;

    for (int i = t; i < Lq; i += 128) sm[i] = g_M[bh * Lq + i];
    __syncthreads();

    for (int r = 0; r < U; r++) {
        float bv = -INFINITY; int bi = 0x7fffffff;
        for (int i = t; i < Lq; i += 128) {
            float v = sm[i];
            if (v > bv || (v == bv && i < bi)) { bv = v; bi = i; }
        }
        rv[t] = bv; ri[t] = bi;
        __syncthreads();
        for (int o = 64; o > 0; o >>= 1) {
            if (t < o) {
                float v2 = rv[t + o]; int i2 = ri[t + o];
                if (v2 > rv[t] || (v2 == rv[t] && i2 < ri[t])) { rv[t] = v2; ri[t] = i2; }
            }
            __syncthreads();
        }
        if (t == 0) { g_top[bh * U + r] = ri[0]; sm[ri[0]] = -INFINITY; }
        __syncthreads();
    }
}

// ---------------------------------------------------------------------------
// Kernel 3a: V mean partials; grid = bh*NCH, 256 threads
// ---------------------------------------------------------------------------
__global__ void __launch_bounds__(256)
k_vmean_part(const float* __restrict__ v)
{
    int blk = blockIdx.x;
    int bh = blk >> 3, ch = blk & 7;
    int b = bh / Hq, h = bh % Hq;
    int t = threadIdx.x;
    int d = t & 63, g = t >> 6;          // 4 l-groups x 64 d
    float acc = 0.f;
    int lend = (ch + 1) * CHK;
    for (int l = ch * CHK + g; l < lend; l += 4)
        acc += v[((size_t)(b * Lq + l) * Hq + h) * Dq + d];
    __shared__ float red[256];
    red[t] = acc;
    __syncthreads();
    if (t < 128) red[t] += red[t + 128];
    __syncthreads();
    if (t < 64) g_vpart[(bh * NCH + ch) * Dq + t] = red[t] + red[t + 64];
    (void)d;
}

// ---------------------------------------------------------------------------
// Kernel 3b: V mean finish; grid = bh, 64 threads
// ---------------------------------------------------------------------------
__global__ void __launch_bounds__(64)
k_vmean_fin()
{
    int bh = blockIdx.x;
    int d = threadIdx.x;
    float s = 0.f;
#pragma unroll
    for (int c = 0; c < NCH; c++) s += g_vpart[(bh * NCH + c) * Dq + d];
    ((float*)g_vmean4)[bh * Dq + d] = s * (1.0f / (float)Lq);
}

// ---------------------------------------------------------------------------
// Kernel 4: broadcast V-mean into context output, float4 stores
// total float4 = Bq*Lq*Hq*Dq/4 = 2^21 ; per-b pattern repeats every 128 float4
// ---------------------------------------------------------------------------
__global__ void __launch_bounds__(256)
k_bcast(float4* __restrict__ out4)
{
    int f = blockIdx.x * 256 + threadIdx.x;
    int b = f >> 19;                      // f / (Lq*Hq*Dq/4)
    out4[f] = g_vmean4[(b << 7) + (f & 127)];
}

// ---------------------------------------------------------------------------
// Kernel 5a: raw scores for top-u queries; grid = bh*NCH, 256 threads
// ---------------------------------------------------------------------------
__global__ void __launch_bounds__(256)
k_scores(const float* __restrict__ q, const float* __restrict__ k)
{
    int blk = blockIdx.x;
    int bh = blk >> 3, ch = blk & 7;
    int b = bh / Hq, h = bh % Hq;
    int t = threadIdx.x;

    __shared__ float qr[U * Dq];
    for (int i = t; i < U * Dq; i += 256) {
        int r = i >> 6, d = i & 63;
        int l = g_top[bh * U + r];
        qr[i] = q[((size_t)(b * Lq + l) * Hq + h) * Dq + d];
    }
    __syncthreads();

    const float scale = 0.125f;
    int kend = (ch + 1) * CHK;
    for (int kk = ch * CHK + t; kk < kend; kk += 256) {
        const float4* krow = (const float4*)(k + ((size_t)(b * Lq + kk) * Hq + h) * Dq);
        float dot[U];
#pragma unroll
        for (int r = 0; r < U; r++) dot[r] = 0.f;
#pragma unroll
        for (int i = 0; i < Dq / 4; i++) {
            float4 kv = krow[i];
#pragma unroll
            for (int r = 0; r < U; r++) {
                dot[r] += kv.x * qr[r * Dq + 4 * i + 0]
                        + kv.y * qr[r * Dq + 4 * i + 1]
                        + kv.z * qr[r * Dq + 4 * i + 2]
                        + kv.w * qr[r * Dq + 4 * i + 3];
            }
        }
#pragma unroll
        for (int r = 0; r < U; r++) g_scores[((size_t)(bh * U + r)) * Lq + kk] = dot[r] * scale;
    }
}

// ---------------------------------------------------------------------------
// Kernel 5b: softmax per row + attn output write; grid = bh*U, 512 threads
// ---------------------------------------------------------------------------
__global__ void __launch_bounds__(512)
k_softmax(float* __restrict__ out)
{
    int blk = blockIdx.x;                 // = bh*U + r, matches attn layout (b,h,u,l)
    float* row = g_scores + (size_t)blk * Lq;
    __shared__ float sr[Lq];
    __shared__ float red[512];
    int t = threadIdx.x;

    float mx = -INFINITY;
    for (int kk = t; kk < Lq; kk += 512) {
        float s = row[kk];
        sr[kk] = s;
        mx = fmaxf(mx, s);
    }
    red[t] = mx; __syncthreads();
    for (int o = 256; o > 0; o >>= 1) {
        if (t < o) red[t] = fmaxf(red[t], red[t + o]);
        __syncthreads();
    }
    mx = red[0]; __syncthreads();

    float sm = 0.f;
    for (int kk = t; kk < Lq; kk += 512) {
        float e = expf(sr[kk] - mx);
        sr[kk] = e;
        sm += e;
    }
    red[t] = sm; __syncthreads();
    for (int o = 256; o > 0; o >>= 1) {
        if (t < o) red[t] += red[t + o];
        __syncthreads();
    }
    float inv = 1.0f / red[0];

    float* attn = out + (size_t)Bq * Lq * Hq * Dq + (size_t)blk * Lq;
    for (int kk = t; kk < Lq; kk += 512) {
        float a = sr[kk] * inv;
        row[kk] = a;
        attn[kk] = a;
    }
}

// ---------------------------------------------------------------------------
// Kernel 5c: ctx partials over K-chunks; grid = bh*NCH, 512 threads
// ---------------------------------------------------------------------------
__global__ void __launch_bounds__(512)
k_ctx(const float* __restrict__ v)
{
    int blk = blockIdx.x;
    int bh = blk >> 3, ch = blk & 7;
    int b = bh / Hq, h = bh % Hq;
    int t = threadIdx.x;
    int d = t & 63, g = t >> 6;           // 8 k-groups x 64 d

    const float* sc = g_scores + (size_t)bh * U * Lq;
    float acc[U];
#pragma unroll
    for (int r = 0; r < U; r++) acc[r] = 0.f;

    int kend = (ch + 1) * CHK;
    for (int kk = ch * CHK + g; kk < kend; kk += 8) {
        float vv = v[((size_t)(b * Lq + kk) * Hq + h) * Dq + d];
#pragma unroll
        for (int r = 0; r < U; r++) acc[r] += sc[r * Lq + kk] * vv;
    }

    __shared__ float cred[8 * U * Dq];
#pragma unroll
    for (int r = 0; r < U; r++) cred[((g * U + r) << 6) + d] = acc[r];
    __syncthreads();

    for (int i = t; i < U * Dq; i += 512) {
        int r = i >> 6, dd = i & 63;
        float s = 0.f;
#pragma unroll
        for (int gg = 0; gg < 8; gg++) s += cred[((gg * U + r) << 6) + dd];
        g_ctxpart[(size_t)(bh * NCH + ch) * U * Dq + i] = s;
    }
}

// ---------------------------------------------------------------------------
// Kernel 5d: reduce chunk partials + scatter into context; grid = bh, 512 threads
// ---------------------------------------------------------------------------
__global__ void __launch_bounds__(512)
k_scatter(float* __restrict__ out)
{
    int bh = blockIdx.x;
    int b = bh / Hq, h = bh % Hq;
    for (int i = threadIdx.x; i < U * Dq; i += 512) {
        int r = i >> 6, d = i & 63;
        float s = 0.f;
#pragma unroll
        for (int c = 0; c < NCH; c++)
            s += g_ctxpart[(size_t)(bh * NCH + c) * U * Dq + i];
        int l = g_top[bh * U + r];
        out[((size_t)(b * Lq + l) * Hq + h) * Dq + d] = s;
    }
}

// ---------------------------------------------------------------------------
extern "C" void kernel_launch(void* const* d_in, const int* in_sizes, int n_in,
                              void* d_out, int out_size)
{
    const float* q   = (const float*)d_in[0];
    const float* k   = (const float*)d_in[1];
    const float* v   = (const float*)d_in[2];
    const int*   idx = (const int*)d_in[3];
    float* out = (float*)d_out;

    (void)in_sizes; (void)n_in; (void)out_size;

    // 1. sampled scores
    k_sample_scores<<<(BH * Lq) / 8, 256>>>(q, k, idx);

    // 2. top-9 per (b,h)
    k_topk<<<BH, 128>>>();

    // 3. V mean (split)
    k_vmean_part<<<BH * NCH, 256>>>(v);
    k_vmean_fin<<<BH, 64>>>();

    // 4. broadcast mean into context (must precede scatter)
    k_bcast<<<(Bq * Lq * Hq * Dq / 4) / 256, 256>>>((float4*)out);

    // 5. scores -> softmax -> ctx partials -> scatter
    k_scores<<<BH * NCH, 256>>>(q, k);
    k_softmax<<<BH * U, 512>>>(out);
    k_ctx<<<BH * NCH, 512>>>(v);
    k_scatter<<<BH, 512>>>(out);
}

// round 5
// speedup vs baseline: 1.6683x; 1.0523x over previous
#include <cuda_runtime.h>
#include <math.h>

#define Bq 4
#define Lq 4096
#define Hq 8
#define Dq 64
#define SK 9
#define U  9
#define BH (Bq*Hq)
#define NCH 8
#define CHK (Lq/NCH)   // 512

// scratch (static __device__ arrays — no allocation)
__device__ float  g_M[BH * Lq];
__device__ int    g_top[BH * U];
__device__ float4 g_vmean4[BH * (Dq/4)];
__device__ float  g_vpart[BH * NCH * Dq];
__device__ float  g_cand_v[BH * NCH * U];
__device__ int    g_cand_i[BH * NCH * U];
__device__ float  g_scores[BH * U * Lq];        // raw scores, then normalized attn
__device__ float  g_ctxpart[BH * NCH * U * Dq];

// ---------------------------------------------------------------------------
// Kernel 1: M[b,h,l] = max_s(Q[l]·K[idx[l,s]]) - sum_s(...)/L
// one warp per (b,h,l); each half-warp computes one sampled dot via float4
// ---------------------------------------------------------------------------
__global__ void __launch_bounds__(256)
k_sample_scores(const float* __restrict__ q,
                const float* __restrict__ k,
                const int*   __restrict__ idx)
{
    int warp = (blockIdx.x * blockDim.x + threadIdx.x) >> 5;
    int lane = threadIdx.x & 31;
    if (warp >= BH * Lq) return;
    int l  = warp % Lq;
    int bh = warp / Lq;
    int b = bh / Hq, h = bh % Hq;

    const float4* qrow = (const float4*)(q + ((size_t)(b * Lq + l) * Hq + h) * Dq);
    float4 q4 = qrow[lane & 15];
    int half = lane >> 4;                 // 0 or 1

    float mx = -INFINITY, sm = 0.f;
#pragma unroll
    for (int s = 0; s < SK; s += 2) {
        int s2 = s + half;
        if (s2 >= SK) s2 = SK - 1;
        int ks = idx[l * SK + s2];
        const float4* krow = (const float4*)(k + ((size_t)(b * Lq + ks) * Hq + h) * Dq);
        float4 kv = krow[lane & 15];
        float p = kv.x * q4.x + kv.y * q4.y + kv.z * q4.z + kv.w * q4.w;
        // reduce within each 16-lane half
        p += __shfl_xor_sync(0xffffffffu, p, 1);
        p += __shfl_xor_sync(0xffffffffu, p, 2);
        p += __shfl_xor_sync(0xffffffffu, p, 4);
        p += __shfl_xor_sync(0xffffffffu, p, 8);
        float p0 = __shfl_sync(0xffffffffu, p, 0);
        float p1 = __shfl_sync(0xffffffffu, p, 16);
        mx = fmaxf(mx, p0); sm += p0;
        if (s + 1 < SK) { mx = fmaxf(mx, p1); sm += p1; }
    }
    if (lane == 0) g_M[bh * Lq + l] = mx - sm * (1.0f / (float)Lq);
}

// ---------------------------------------------------------------------------
// Kernel 2a: per-chunk top-9; grid = bh*NCH, 128 threads
// ---------------------------------------------------------------------------
__global__ void __launch_bounds__(128)
k_topk_part()
{
    int blk = blockIdx.x;
    int bh = blk >> 3, ch = blk & 7;
    int base = ch * CHK;
    int t = threadIdx.x;

    __shared__ float sv[CHK];
    __shared__ float rv[128];
    __shared__ int   ri[128];

    for (int i = t; i < CHK; i += 128) sv[i] = g_M[bh * Lq + base + i];
    __syncthreads();

    for (int r = 0; r < U; r++) {
        float bv = -INFINITY; int bi = 0x7fffffff;
#pragma unroll
        for (int j = 0; j < CHK / 128; j++) {
            int i = t + j * 128;
            float v = sv[i];
            if (v > bv || (v == bv && i < bi)) { bv = v; bi = i; }
        }
        rv[t] = bv; ri[t] = bi;
        __syncthreads();
        for (int o = 64; o > 0; o >>= 1) {
            if (t < o) {
                float v2 = rv[t + o]; int i2 = ri[t + o];
                if (v2 > rv[t] || (v2 == rv[t] && i2 < ri[t])) { rv[t] = v2; ri[t] = i2; }
            }
            __syncthreads();
        }
        if (t == 0) {
            g_cand_v[blk * U + r] = rv[0];
            g_cand_i[blk * U + r] = base + ri[0];
            sv[ri[0]] = -INFINITY;
        }
        __syncthreads();
    }
}

// ---------------------------------------------------------------------------
// Kernel 2b (fused): warp 0 merges 72 candidates -> global top-9;
// threads 32..95 finish the V mean. grid = bh, 128 threads
// ---------------------------------------------------------------------------
__global__ void __launch_bounds__(128)
k_fin()
{
    int bh = blockIdx.x;
    int t = threadIdx.x;

    if (t >= 32 && t < 96) {
        int d = t - 32;
        float s = 0.f;
#pragma unroll
        for (int c = 0; c < NCH; c++) s += g_vpart[(bh * NCH + c) * Dq + d];
        ((float*)g_vmean4)[bh * Dq + d] = s * (1.0f / (float)Lq);
    }

    if (t < 32) {
        // each lane owns candidates t, t+32, t+64 (72 total)
        const int NC = NCH * U;          // 72
        float v0 = -INFINITY, v1 = -INFINITY, v2 = -INFINITY;
        int   i0 = 0x7fffffff, i1 = 0x7fffffff, i2 = 0x7fffffff;
        if (t      < NC) { v0 = g_cand_v[bh * NC + t];      i0 = g_cand_i[bh * NC + t]; }
        if (t + 32 < NC) { v1 = g_cand_v[bh * NC + t + 32]; i1 = g_cand_i[bh * NC + t + 32]; }
        if (t + 64 < NC) { v2 = g_cand_v[bh * NC + t + 64]; i2 = g_cand_i[bh * NC + t + 64]; }

        for (int r = 0; r < U; r++) {
            float bv = v0; int bi = i0;
            if (v1 > bv || (v1 == bv && i1 < bi)) { bv = v1; bi = i1; }
            if (v2 > bv || (v2 == bv && i2 < bi)) { bv = v2; bi = i2; }
#pragma unroll
            for (int o = 16; o > 0; o >>= 1) {
                float ov = __shfl_xor_sync(0xffffffffu, bv, o);
                int   oi = __shfl_xor_sync(0xffffffffu, bi, o);
                if (ov > bv || (ov == bv && oi < bi)) { bv = ov; bi = oi; }
            }
            if (t == 0) g_top[bh * U + r] = bi;
            // retire the winner
            if (i0 == bi) v0 = -INFINITY;
            if (i1 == bi) v1 = -INFINITY;
            if (i2 == bi) v2 = -INFINITY;
        }
    }
}

// ---------------------------------------------------------------------------
// Kernel 3: V mean partials; grid = bh*NCH, 256 threads
// ---------------------------------------------------------------------------
__global__ void __launch_bounds__(256)
k_vmean_part(const float* __restrict__ v)
{
    int blk = blockIdx.x;
    int bh = blk >> 3, ch = blk & 7;
    int b = bh / Hq, h = bh % Hq;
    int t = threadIdx.x;
    int d = t & 63, g = t >> 6;          // 4 l-groups x 64 d
    float acc = 0.f;
    int lend = (ch + 1) * CHK;
    for (int l = ch * CHK + g; l < lend; l += 4)
        acc += v[((size_t)(b * Lq + l) * Hq + h) * Dq + d];
    __shared__ float red[256];
    red[t] = acc;
    __syncthreads();
    if (t < 128) red[t] += red[t + 128];
    __syncthreads();
    if (t < 64) g_vpart[(bh * NCH + ch) * Dq + t] = red[t] + red[t + 64];
}

// ---------------------------------------------------------------------------
// Kernel 4: broadcast V-mean into context output, float4 stores
// ---------------------------------------------------------------------------
__global__ void __launch_bounds__(256)
k_bcast(float4* __restrict__ out4)
{
    int f = blockIdx.x * 256 + threadIdx.x;
    int b = f >> 19;                      // per-b float4 count = 2^19
    out4[f] = g_vmean4[(b << 7) + (f & 127)];
}

// ---------------------------------------------------------------------------
// Kernel 5a: raw scores for top-u queries; grid = bh*NCH, 256 threads
// ---------------------------------------------------------------------------
__global__ void __launch_bounds__(256)
k_scores(const float* __restrict__ q, const float* __restrict__ k)
{
    int blk = blockIdx.x;
    int bh = blk >> 3, ch = blk & 7;
    int b = bh / Hq, h = bh % Hq;
    int t = threadIdx.x;

    __shared__ float qr[U * Dq];
    for (int i = t; i < U * Dq; i += 256) {
        int r = i >> 6, d = i & 63;
        int l = g_top[bh * U + r];
        qr[i] = q[((size_t)(b * Lq + l) * Hq + h) * Dq + d];
    }
    __syncthreads();

    const float scale = 0.125f;
    int kend = (ch + 1) * CHK;
    for (int kk = ch * CHK + t; kk < kend; kk += 256) {
        const float4* krow = (const float4*)(k + ((size_t)(b * Lq + kk) * Hq + h) * Dq);
        float dot[U];
#pragma unroll
        for (int r = 0; r < U; r++) dot[r] = 0.f;
#pragma unroll
        for (int i = 0; i < Dq / 4; i++) {
            float4 kv = krow[i];
#pragma unroll
            for (int r = 0; r < U; r++) {
                dot[r] += kv.x * qr[r * Dq + 4 * i + 0]
                        + kv.y * qr[r * Dq + 4 * i + 1]
                        + kv.z * qr[r * Dq + 4 * i + 2]
                        + kv.w * qr[r * Dq + 4 * i + 3];
            }
        }
#pragma unroll
        for (int r = 0; r < U; r++) g_scores[((size_t)(bh * U + r)) * Lq + kk] = dot[r] * scale;
    }
}

// ---------------------------------------------------------------------------
// Kernel 5b: softmax per row + attn output write; grid = bh*U, 512 threads
// ---------------------------------------------------------------------------
__global__ void __launch_bounds__(512)
k_softmax(float* __restrict__ out)
{
    int blk = blockIdx.x;                 // = bh*U + r, matches attn layout (b,h,u,l)
    float* row = g_scores + (size_t)blk * Lq;
    __shared__ float sr[Lq];
    __shared__ float red[512];
    int t = threadIdx.x;

    float mx = -INFINITY;
    for (int kk = t; kk < Lq; kk += 512) {
        float s = row[kk];
        sr[kk] = s;
        mx = fmaxf(mx, s);
    }
    red[t] = mx; __syncthreads();
    for (int o = 256; o > 0; o >>= 1) {
        if (t < o) red[t] = fmaxf(red[t], red[t + o]);
        __syncthreads();
    }
    mx = red[0]; __syncthreads();

    float sm = 0.f;
    for (int kk = t; kk < Lq; kk += 512) {
        float e = expf(sr[kk] - mx);
        sr[kk] = e;
        sm += e;
    }
    red[t] = sm; __syncthreads();
    for (int o = 256; o > 0; o >>= 1) {
        if (t < o) red[t] += red[t + o];
        __syncthreads();
    }
    float inv = 1.0f / red[0];

    float* attn = out + (size_t)Bq * Lq * Hq * Dq + (size_t)blk * Lq;
    for (int kk = t; kk < Lq; kk += 512) {
        float a = sr[kk] * inv;
        row[kk] = a;
        attn[kk] = a;
    }
}

// ---------------------------------------------------------------------------
// Kernel 5c: ctx partials over K-chunks; grid = bh*NCH, 512 threads
// ---------------------------------------------------------------------------
__global__ void __launch_bounds__(512)
k_ctx(const float* __restrict__ v)
{
    int blk = blockIdx.x;
    int bh = blk >> 3, ch = blk & 7;
    int b = bh / Hq, h = bh % Hq;
    int t = threadIdx.x;
    int d = t & 63, g = t >> 6;           // 8 k-groups x 64 d

    const float* sc = g_scores + (size_t)bh * U * Lq;
    float acc[U];
#pragma unroll
    for (int r = 0; r < U; r++) acc[r] = 0.f;

    int kend = (ch + 1) * CHK;
    for (int kk = ch * CHK + g; kk < kend; kk += 8) {
        float vv = v[((size_t)(b * Lq + kk) * Hq + h) * Dq + d];
#pragma unroll
        for (int r = 0; r < U; r++) acc[r] += sc[r * Lq + kk] * vv;
    }

    __shared__ float cred[8 * U * Dq];
#pragma unroll
    for (int r = 0; r < U; r++) cred[((g * U + r) << 6) + d] = acc[r];
    __syncthreads();

    for (int i = t; i < U * Dq; i += 512) {
        int r = i >> 6, dd = i & 63;
        float s = 0.f;
#pragma unroll
        for (int gg = 0; gg < 8; gg++) s += cred[((gg * U + r) << 6) + dd];
        g_ctxpart[(size_t)(bh * NCH + ch) * U * Dq + i] = s;
    }
}

// ---------------------------------------------------------------------------
// Kernel 5d: reduce chunk partials + scatter into context; grid = bh, 512 threads
// ---------------------------------------------------------------------------
__global__ void __launch_bounds__(512)
k_scatter(float* __restrict__ out)
{
    int bh = blockIdx.x;
    int b = bh / Hq, h = bh % Hq;
    for (int i = threadIdx.x; i < U * Dq; i += 512) {
        int r = i >> 6, d = i & 63;
        float s = 0.f;
#pragma unroll
        for (int c = 0; c < NCH; c++)
            s += g_ctxpart[(size_t)(bh * NCH + c) * U * Dq + i];
        int l = g_top[bh * U + r];
        out[((size_t)(b * Lq + l) * Hq + h) * Dq + d] = s;
    }
}

// ---------------------------------------------------------------------------
extern "C" void kernel_launch(void* const* d_in, const int* in_sizes, int n_in,
                              void* d_out, int out_size)
{
    const float* q   = (const float*)d_in[0];
    const float* k   = (const float*)d_in[1];
    const float* v   = (const float*)d_in[2];
    const int*   idx = (const int*)d_in[3];
    float* out = (float*)d_out;

    (void)in_sizes; (void)n_in; (void)out_size;

    // 1. sampled scores
    k_sample_scores<<<(BH * Lq) / 8, 256>>>(q, k, idx);

    // 2/3. V mean partials + per-chunk top-9 (independent, both full-chip)
    k_vmean_part<<<BH * NCH, 256>>>(v);
    k_topk_part<<<BH * NCH, 128>>>();

    // fused: top-9 merge + V mean finish
    k_fin<<<BH, 128>>>();

    // 4. broadcast mean into context (must precede scatter)
    k_bcast<<<(Bq * Lq * Hq * Dq / 4) / 256, 256>>>((float4*)out);

    // 5. scores -> softmax -> ctx partials -> scatter
    k_scores<<<BH * NCH, 256>>>(q, k);
    k_softmax<<<BH * U, 512>>>(out);
    k_ctx<<<BH * NCH, 512>>>(v);
    k_scatter<<<BH, 512>>>(out);
}